// round 13
// baseline (speedup 1.0000x reference)
#include <cuda_runtime.h>
#include <cuda_bf16.h>

#define VSA_N     2048
#define VSA_BLK   512            // 16 warps
#define VSA_ROWS  32             // lane owns a row
#define VSA_PAIRS (VSA_N / 2)    // 1024 j-pairs
#define VSA_PSEG  (VSA_PAIRS / (VSA_BLK / 32))  // 64 pairs per warp

typedef unsigned long long ull;

// Packed f32x2 helpers (Blackwell; operands come pre-paired from the tile).
#define F32X2_MUL(d, a, b) \
    asm("mul.rn.f32x2 %0, %1, %2;" : "=l"(d) : "l"(a), "l"(b))
#define F32X2_ADD(d, a, b) \
    asm("add.rn.f32x2 %0, %1, %2;" : "=l"(d) : "l"(a), "l"(b))
#define F32X2_FMA(d, a, b, c) \
    asm("fma.rn.f32x2 %0, %1, %2, %3;" : "=l"(d) : "l"(a), "l"(b), "l"(c))
#define F32X2_PACK(d, lo, hi) \
    asm("mov.b64 %0, {%1, %2};" : "=l"(d) : "f"(lo), "f"(hi))
#define F32X2_UNPACK(lo, hi, s) \
    asm("mov.b64 {%0, %1}, %2;" : "=f"(lo), "=f"(hi) : "l"(s))

// ---------------------------------------------------------------------------
// Fused kernel, transposed broadcast + PACKED-J f32x2 math.
// grid = (64, B), 512 threads (16 warps).
//   * lane l owns row i = bx*32 + l (private packed accumulators)
//   * warp w covers j-PAIRS [w*64, (w+1)*64): each f32x2 op handles 2 j's
//   * all lanes of a warp read the same tile entry -> LDS broadcast
//
// Tile layout per j-pair p (32 B): (x0,x1)(y0,y1) | (z0,z1)(kk0,kk1)
// -> two LDS.128 yield four ready f32x2 operands, ZERO pack movs.
// k' = (k - mk) / sqrt(N); kk = |k'|^2.
//
// Math per j-pair (2 pairs of (i,j)):
//   dot2 = q.k'        3 fma2
//   d2   = dot2*dot2   1 mul2      nd2 = -d2 via xor.b64 (1 alu)
//   n2   = qq*kk - d2  1 fma2
//   unpack n2, eta = sqrt.approx(|n2|)        (1 MUFU per j; fabs folds)
//   e    = Taylor5(eta) scalar Horner          (5 FFMA-imm per j, rt=1)
//   pack e2; Z += e2 (1 add2); W += e2*k' (3 fma2)
// Replaces per-pair 2 MUFU (rt=8 -> was an ~8us floor) with 1, and halves
// FMA-pipe cycles (scalar FFMA rt=2 vs FFMA2 rt=2 for 2 lanes of work).
// ---------------------------------------------------------------------------
__global__ __launch_bounds__(VSA_BLK, 2)
void vsa_fused_kernel(const float* __restrict__ q,
                      const float* __restrict__ k,
                      const float* __restrict__ v,
                      float* __restrict__ out) {
    __shared__ double2 sk2[VSA_PAIRS * 2];   // 32 KB; reused for partials
    __shared__ float   red[VSA_BLK / 32][9];
    __shared__ float   means[9];

    const int tid  = threadIdx.x;
    const int b    = blockIdx.y;
    const int warp = tid >> 5;
    const int lane = tid & 31;

    const float* qb = q + (size_t)b * VSA_N * 3;
    const float* kb = k + (size_t)b * VSA_N * 3;
    const float* vb = v + (size_t)b * VSA_N * 3;

    // ---- Phase A: per-batch means (block-redundant, L2-resident) ----
    {
        float s[9];
#pragma unroll
        for (int c = 0; c < 9; c++) s[c] = 0.0f;

#pragma unroll
        for (int r = 0; r < VSA_N / VSA_BLK; r++) {
            const int o = (tid + r * VSA_BLK) * 3;
            s[0] += qb[o + 0]; s[1] += qb[o + 1]; s[2] += qb[o + 2];
            s[3] += kb[o + 0]; s[4] += kb[o + 1]; s[5] += kb[o + 2];
            s[6] += vb[o + 0]; s[7] += vb[o + 1]; s[8] += vb[o + 2];
        }
#pragma unroll
        for (int c = 0; c < 9; c++) {
#pragma unroll
            for (int off = 16; off > 0; off >>= 1)
                s[c] += __shfl_xor_sync(0xFFFFFFFFu, s[c], off);
        }
        if (lane == 0) {
#pragma unroll
            for (int c = 0; c < 9; c++) red[warp][c] = s[c];
        }
        __syncthreads();
        if (tid < 9) {
            float t = 0.0f;
#pragma unroll
            for (int w = 0; w < VSA_BLK / 32; w++) t += red[w][tid];
            means[tid] = t * (1.0f / (float)VSA_N);
        }
        __syncthreads();
    }

    const float mqx = means[0], mqy = means[1], mqz = means[2];
    const float mkx = means[3], mky = means[4], mkz = means[5];
    const float mvx = means[6], mvy = means[7], mvz = means[8];

    const float cs = 0.022097086912079612f;  // 1/sqrt(2048) (natural exp now)

    // ---- Phase B: stage k' pair-interleaved ----
    {
        float* skf = (float*)sk2;
        for (int j = tid; j < VSA_N; j += VSA_BLK) {
            const float kx = (kb[j * 3 + 0] - mkx) * cs;
            const float ky = (kb[j * 3 + 1] - mky) * cs;
            const float kz = (kb[j * 3 + 2] - mkz) * cs;
            const float kk = fmaf(kx, kx, fmaf(ky, ky, kz * kz));
            const int base = (j >> 1) * 8 + (j & 1);
            skf[base + 0] = kx;
            skf[base + 2] = ky;
            skf[base + 4] = kz;
            skf[base + 6] = kk;
        }
    }
    __syncthreads();

    // ---- Phase C: hot loop ----
    const int i = blockIdx.x * VSA_ROWS + lane;

    const float qx = qb[i * 3 + 0] - mqx;
    const float qy = qb[i * 3 + 1] - mqy;
    const float qz = qb[i * 3 + 2] - mqz;
    const float qq = fmaf(qx, qx, fmaf(qy, qy, qz * qz));

    ull qx2, qy2, qz2, qq2;
    F32X2_PACK(qx2, qx, qx);
    F32X2_PACK(qy2, qy, qy);
    F32X2_PACK(qz2, qz, qz);
    F32X2_PACK(qq2, qq, qq);

    ull Z2 = 0ull, Wx2 = 0ull, Wy2 = 0ull, Wz2 = 0ull;
    const ull signmask = 0x8000000080000000ull;

    const double2* p = sk2 + warp * (VSA_PSEG * 2);

#pragma unroll 2
    for (int t = 0; t < VSA_PSEG; t++) {
        const double2 d0 = p[2 * t + 0];   // (x0,x1)(y0,y1)
        const double2 d1 = p[2 * t + 1];   // (z0,z1)(kk0,kk1)
        const ull kx2 = (ull)__double_as_longlong(d0.x);
        const ull ky2 = (ull)__double_as_longlong(d0.y);
        const ull kz2 = (ull)__double_as_longlong(d1.x);
        const ull kk2 = (ull)__double_as_longlong(d1.y);

        ull dot2, d2, nd2, n2;
        F32X2_MUL(dot2, qx2, kx2);
        F32X2_FMA(dot2, qy2, ky2, dot2);
        F32X2_FMA(dot2, qz2, kz2, dot2);
        F32X2_MUL(d2, dot2, dot2);
        asm("xor.b64 %0, %1, %2;" : "=l"(nd2) : "l"(d2), "l"(signmask));
        F32X2_FMA(n2, qq2, kk2, nd2);     // n2 = qq*kk - dot^2 (>= 0 up to fp)

        float na, nb;
        F32X2_UNPACK(na, nb, n2);
        float ea, eb;
        asm("sqrt.approx.f32 %0, %1;" : "=f"(ea) : "f"(fabsf(na)));
        asm("sqrt.approx.f32 %0, %1;" : "=f"(eb) : "f"(fabsf(nb)));

        // e = exp(eta), eta <= ~0.44 -> order-5 Taylor, rel err <= ~2e-5
        float ta = fmaf(ea, 8.3333333e-3f, 4.1666668e-2f);  // 1/120, 1/24
        float tb = fmaf(eb, 8.3333333e-3f, 4.1666668e-2f);
        ta = fmaf(ea, ta, 0.16666667f);
        tb = fmaf(eb, tb, 0.16666667f);
        ta = fmaf(ea, ta, 0.5f);
        tb = fmaf(eb, tb, 0.5f);
        ta = fmaf(ea, ta, 1.0f);
        tb = fmaf(eb, tb, 1.0f);
        const float Ea = fmaf(ea, ta, 1.0f);
        const float Eb = fmaf(eb, tb, 1.0f);

        ull e2;
        F32X2_PACK(e2, Ea, Eb);
        F32X2_ADD(Z2, Z2, e2);
        F32X2_FMA(Wx2, e2, kx2, Wx2);
        F32X2_FMA(Wy2, e2, ky2, Wy2);
        F32X2_FMA(Wz2, e2, kz2, Wz2);
    }

    // Collapse packed j-halves.
    float Z, Wx, Wy, Wz;
    {
        float a0, a1;
        F32X2_UNPACK(a0, a1, Z2);  Z  = a0 + a1;
        F32X2_UNPACK(a0, a1, Wx2); Wx = a0 + a1;
        F32X2_UNPACK(a0, a1, Wy2); Wy = a0 + a1;
        F32X2_UNPACK(a0, a1, Wz2); Wz = a0 + a1;
    }

    // ---- Phase D: cross-warp reduction (16 warps of partials per row) ----
    __syncthreads();                     // everyone done reading sk2
    float4* part = (float4*)sk2;         // part[warp*33 + lane], padded
    part[warp * 33 + lane] = make_float4(Z, Wx, Wy, Wz);
    __syncthreads();

    {
        // warp w reduces rows w (lanes 0..15) and w+16 (lanes 16..31)
        const int srcw = lane & 15;
        const int row  = warp + 16 * (lane >> 4);
        const float4 pp = part[srcw * 33 + row];
        float Zr = pp.x, Wxr = pp.y, Wyr = pp.z, Wzr = pp.w;
#pragma unroll
        for (int off = 8; off > 0; off >>= 1) {
            Zr  += __shfl_xor_sync(0xFFFFFFFFu, Zr,  off);
            Wxr += __shfl_xor_sync(0xFFFFFFFFu, Wxr, off);
            Wyr += __shfl_xor_sync(0xFFFFFFFFu, Wyr, off);
            Wzr += __shfl_xor_sync(0xFFFFFFFFu, Wzr, off);
        }

        if ((lane & 15) == 0) {
            const int ir = blockIdx.x * VSA_ROWS + row;
            const float qxr = qb[ir * 3 + 0] - mqx;
            const float qyr = qb[ir * 3 + 1] - mqy;
            const float qzr = qb[ir * 3 + 2] - mqz;
            // T' = q x W (= cs * T);  u = cross(T, v_c) / (Z * N)
            const float Tx = fmaf(qyr, Wzr, -qzr * Wyr);
            const float Ty = fmaf(qzr, Wxr, -qxr * Wzr);
            const float Tz = fmaf(qxr, Wyr, -qyr * Wxr);
            const float vx = vb[ir * 3 + 0] - mvx;
            const float vy = vb[ir * 3 + 1] - mvy;
            const float vz = vb[ir * 3 + 2] - mvz;
            const float inv = 1.0f / (Zr * (float)VSA_N * cs);
            float* o = out + ((size_t)b * VSA_N + ir) * 3;
            o[0] = fmaf(Ty, vz, -Tz * vy) * inv;
            o[1] = fmaf(Tz, vx, -Tx * vz) * inv;
            o[2] = fmaf(Tx, vy, -Ty * vx) * inv;
        }
    }
}

// ---------------------------------------------------------------------------
extern "C" void kernel_launch(void* const* d_in, const int* in_sizes, int n_in,
                              void* d_out, int out_size) {
    const float* q = (const float*)d_in[0];
    const float* k = (const float*)d_in[1];
    const float* v = (const float*)d_in[2];
    float* out = (float*)d_out;

    const int B = out_size / (VSA_N * 3);   // = 4

    dim3 grid(VSA_N / VSA_ROWS, B);         // (64, 4) = 256 blocks
    vsa_fused_kernel<<<grid, VSA_BLK>>>(q, k, v, out);
}

// round 14
// speedup vs baseline: 1.0137x; 1.0137x over previous
#include <cuda_runtime.h>
#include <cuda_bf16.h>

#define VSA_N    2048
#define VSA_BLK  512           // 16 warps
#define VSA_ROWS 16            // rows per block; lane l -> row (l & 15)
// j-streams: 16 warps * 2 half-warps = 32 streams of 64 j's each.

// ---------------------------------------------------------------------------
// Fused kernel, DOUBLED WARP SUPPLY. grid = (2048/16, B) = (128, 4) = 512
// blocks x 16 warps = 8192 warps (R13 diagnosis: every config since R10
// supplied only ~4096 warps against 9472 slots -> 43% occupancy ceiling was
// the plateau, not the pipes).
//
//   * lane l owns row i = bx*16 + (l & 15): private Z,W accumulators
//   * j-stream s = warp*2 + (l >> 4): covers j in [s*64, s*64+64)
//   * LDS per iter: 2 half-warp broadcasts (2 distinct float4 per warp)
//
// Hot-loop math (proven since R6): T_i = q_i x (sum_j e_ij k_j) (bilinear),
// |q x k|^2 = |q|^2|k|^2 - (q.k)^2 (Lagrange), e = ex2(sqrt(n2')) with k
// pre-scaled by c1 = log2e/sqrt(N). 32 regs, no spills.
// ---------------------------------------------------------------------------
__global__ __launch_bounds__(VSA_BLK, 4)
void vsa_fused_kernel(const float* __restrict__ q,
                      const float* __restrict__ k,
                      const float* __restrict__ v,
                      float* __restrict__ out) {
    __shared__ float4 sk[VSA_N];           // 32 KB; reused for partials
    __shared__ float  red[VSA_BLK / 32][9];
    __shared__ float  means[9];

    const int tid  = threadIdx.x;
    const int b    = blockIdx.y;
    const int warp = tid >> 5;
    const int lane = tid & 31;

    const float* qb = q + (size_t)b * VSA_N * 3;
    const float* kb = k + (size_t)b * VSA_N * 3;
    const float* vb = v + (size_t)b * VSA_N * 3;

    // ---- Phase A: per-batch means (block-redundant, L2-resident) ----
    {
        float s[9];
#pragma unroll
        for (int c = 0; c < 9; c++) s[c] = 0.0f;

#pragma unroll
        for (int r = 0; r < VSA_N / VSA_BLK; r++) {
            const int o = (tid + r * VSA_BLK) * 3;
            s[0] += qb[o + 0]; s[1] += qb[o + 1]; s[2] += qb[o + 2];
            s[3] += kb[o + 0]; s[4] += kb[o + 1]; s[5] += kb[o + 2];
            s[6] += vb[o + 0]; s[7] += vb[o + 1]; s[8] += vb[o + 2];
        }
#pragma unroll
        for (int c = 0; c < 9; c++) {
#pragma unroll
            for (int off = 16; off > 0; off >>= 1)
                s[c] += __shfl_xor_sync(0xFFFFFFFFu, s[c], off);
        }
        if (lane == 0) {
#pragma unroll
            for (int c = 0; c < 9; c++) red[warp][c] = s[c];
        }
        __syncthreads();
        if (tid < 9) {
            float t = 0.0f;
#pragma unroll
            for (int w = 0; w < VSA_BLK / 32; w++) t += red[w][tid];
            means[tid] = t * (1.0f / (float)VSA_N);
        }
        __syncthreads();
    }

    const float mqx = means[0], mqy = means[1], mqz = means[2];
    const float mkx = means[3], mky = means[4], mkz = means[5];
    const float mvx = means[6], mvy = means[7], mvz = means[8];

    // c1 = log2(e) / sqrt(2048)
    const float c1 = 1.4426950408889634f * 0.022097086912079612f;

    // ---- Phase B: stage k' = (k-mk)*c1 as float4 (xyz, |k'|^2) ----
#pragma unroll
    for (int r = 0; r < VSA_N / VSA_BLK; r++) {
        const int j = tid + r * VSA_BLK;
        const float kx = (kb[j * 3 + 0] - mkx) * c1;
        const float ky = (kb[j * 3 + 1] - mky) * c1;
        const float kz = (kb[j * 3 + 2] - mkz) * c1;
        const float kk = fmaf(kx, kx, fmaf(ky, ky, kz * kz));
        sk[j] = make_float4(kx, ky, kz, kk);
    }
    __syncthreads();

    // ---- Phase C: hot loop. Row = lane&15; j-stream = warp*2 + (lane>>4) ----
    const int row    = lane & 15;
    const int stream = warp * 2 + (lane >> 4);   // 0..31
    const int i      = blockIdx.x * VSA_ROWS + row;

    const float qx = qb[i * 3 + 0] - mqx;
    const float qy = qb[i * 3 + 1] - mqy;
    const float qz = qb[i * 3 + 2] - mqz;
    const float qq = fmaf(qx, qx, fmaf(qy, qy, qz * qz));

    float Z = 0.0f, Wx = 0.0f, Wy = 0.0f, Wz = 0.0f;

    const float4* pj = sk + stream * 64;
#pragma unroll 4
    for (int jj = 0; jj < 64; jj++) {
        const float4 f = pj[jj];   // half-warp broadcast (2 lines per warp)
        const float dot = fmaf(qx, f.x, fmaf(qy, f.y, qz * f.z));
        const float n2 = fabsf(fmaf(-dot, dot, qq * f.w));
        float e;
        asm("sqrt.approx.f32 %0, %1;" : "=f"(e) : "f"(n2));
        asm("ex2.approx.f32 %0, %1;"  : "=f"(e) : "f"(e));
        Z += e;
        Wx = fmaf(e, f.x, Wx);
        Wy = fmaf(e, f.y, Wy);
        Wz = fmaf(e, f.z, Wz);
    }

    // ---- Phase D: reduce 32 stream-partials per row ----
    // part[stream * 17 + row] (stride 17 -> 4-way worst-case conflicts,
    // one-time cost). 32*17 = 544 float4 fits in the reused sk buffer.
    __syncthreads();   // all warps done reading sk
    float4* part = sk;
    part[stream * 17 + row] = make_float4(Z, Wx, Wy, Wz);
    __syncthreads();

    // Warp r (r < 16) reduces row r: lane l holds stream-l's partial.
    if (warp < VSA_ROWS) {
        const float4 p = part[lane * 17 + warp];
        float Zr = p.x, Wxr = p.y, Wyr = p.z, Wzr = p.w;
#pragma unroll
        for (int off = 16; off > 0; off >>= 1) {
            Zr  += __shfl_xor_sync(0xFFFFFFFFu, Zr,  off);
            Wxr += __shfl_xor_sync(0xFFFFFFFFu, Wxr, off);
            Wyr += __shfl_xor_sync(0xFFFFFFFFu, Wyr, off);
            Wzr += __shfl_xor_sync(0xFFFFFFFFu, Wzr, off);
        }

        if (lane == 0) {
            const int ir = blockIdx.x * VSA_ROWS + warp;
            const float qxr = qb[ir * 3 + 0] - mqx;
            const float qyr = qb[ir * 3 + 1] - mqy;
            const float qzr = qb[ir * 3 + 2] - mqz;
            // T' = q x W (= c1 * T);  u = cross(T, v_c) / (Z * N)
            const float Tx = fmaf(qyr, Wzr, -qzr * Wyr);
            const float Ty = fmaf(qzr, Wxr, -qxr * Wzr);
            const float Tz = fmaf(qxr, Wyr, -qyr * Wxr);
            const float vx = vb[ir * 3 + 0] - mvx;
            const float vy = vb[ir * 3 + 1] - mvy;
            const float vz = vb[ir * 3 + 2] - mvz;
            const float inv = 1.0f / (Zr * (float)VSA_N * c1);
            float* o = out + ((size_t)b * VSA_N + ir) * 3;
            o[0] = fmaf(Ty, vz, -Tz * vy) * inv;
            o[1] = fmaf(Tz, vx, -Tx * vz) * inv;
            o[2] = fmaf(Tx, vy, -Ty * vx) * inv;
        }
    }
}

// ---------------------------------------------------------------------------
extern "C" void kernel_launch(void* const* d_in, const int* in_sizes, int n_in,
                              void* d_out, int out_size) {
    const float* q = (const float*)d_in[0];
    const float* k = (const float*)d_in[1];
    const float* v = (const float*)d_in[2];
    float* out = (float*)d_out;

    const int B = out_size / (VSA_N * 3);   // = 4

    dim3 grid(VSA_N / VSA_ROWS, B);         // (128, 4) = 512 blocks
    vsa_fused_kernel<<<grid, VSA_BLK>>>(q, k, v, out);
}